// round 15
// baseline (speedup 1.0000x reference)
#include <cuda_runtime.h>

// Problem constants (fixed by the dataset)
#define BB   16
#define NN   32
#define HH   512
#define WW   512
#define CC   512
#define SS   256    // 16*16 pooled spatial
#define EE   128

// Scratch (static device globals — zero-initialized at load; kernelB restores
// the zeroed state after each use so graph replays stay deterministic).
__device__ float g_obj[BB * NN * EE];    // 256 KB: pooled numerators (REDG accum)
__device__ float g_mr[BB * NN * SS];     // resized masks [bn][s]
__device__ float g_minv[BB * NN];        // 1/(mask_sum + eps)
__device__ float g_w1T[EE * EE];         // w1 transposed [k][e]
__device__ float g_w2T[EE * EE];         // w2 transposed [k][e]
__device__ int   g_ctr;                  // mask blocks done (target 512)

// Swizzled index into the 64x64 proj staging tile (quad rotation).
__device__ __forceinline__ int sp_idx(int ls, int e) {
    return ls * 64 + ((((e >> 2) + (ls >> 2)) & 15) << 2) + (e & 3);
}

// Per-warpgroup single-buffered K-tile storage (four independent quarters).
// Each quarter: W tile 16x68 (1088) + F tile 16x68 (1088) = 2176 floats.
#define SW1(g,k,e) sBuf[(g)*2176 + (k)*68 + (e)]
#define SF1(g,k,s) sBuf[(g)*2176 + 1088 + (k)*68 + (s)]

// ---------------------------------------------------------------------------
// Kernel A (512 threads/block, grid 642):
//   blocks [0,128):   GEMM 64Ex64S, 4-way in-block split-K: warpgroup g does
//                     K in [128g, 128g+128), 8Ex4S microtile, single-buffered
//                     16-k tiles (4 warps/SMSP saturate the FFMA pipe).
//                     Partials combined via a 2-round smem tree, BN/ReLU,
//                     pooling GEMM2 -> REDG into g_obj.
//   blocks [128,640): bilinear mask resize + sums -> g_ctr.
//   blocks 640,641:   transpose w1/w2 -> g_w1T/g_w2T.
// ---------------------------------------------------------------------------
__global__ void __launch_bounds__(512) kernelA(
    const float* __restrict__ features,   // [B, C, 16, 16]
    const float* __restrict__ masks,      // [B, N, 512, 512]
    const float* __restrict__ conv_w,     // [E, C]
    const float* __restrict__ conv_b,
    const float* __restrict__ bn_gamma, const float* __restrict__ bn_beta,
    const float* __restrict__ bn_mean,  const float* __restrict__ bn_var,
    const float* __restrict__ w1, const float* __restrict__ w2)
{
    __shared__ float sBuf[8704];          // 4 wg quarters; later stages + sP
    __shared__ float smr[NN][64];         // mask tile [n][local s]
    __shared__ float red[16];

    const int blk = blockIdx.x;
    const int tid = threadIdx.x;

    if (blk >= 640) {
        // ---------------- weight transpose path (aliases sBuf) -------------
        float (*ttile)[33] = (float (*)[33])sBuf;
        const float* src = (blk == 640) ? w1 : w2;
        float* dstT      = (blk == 640) ? g_w1T : g_w2T;
        const int rr = tid >> 5;            // 0..15
        const int cc = tid & 31;
        for (int t = 0; t < 16; t++) {
            const int ti = t >> 2, tj = t & 3;
            #pragma unroll
            for (int q = 0; q < 2; q++) {
                const int row = q * 16 + rr;
                ttile[row][cc] = src[(size_t)(ti * 32 + row) * EE + tj * 32 + cc];
            }
            __syncthreads();
            #pragma unroll
            for (int q = 0; q < 2; q++) {
                const int row = q * 16 + rr;
                dstT[(size_t)(tj * 32 + row) * EE + ti * 32 + cc] = ttile[cc][row];
            }
            __syncthreads();
        }
        return;
    }

    if (blk >= 128) {
        // ---------------- mask resize path (one pixel per thread, tid<256) --
        const int bn = blk - 128;                 // 0..511
        const float* m = masks + (size_t)bn * (HH * WW);
        float lsum = 0.0f;

        if (tid < 256) {
            const int o = tid >> 4;               // out row 0..15
            const int p = tid & 15;               // out col 0..15
            float sy = (o + 0.5f) * ((float)HH / 16.0f) - 0.5f;
            sy = fmaxf(sy, 0.0f);
            int   y0 = (int)floorf(sy);
            float fy = sy - (float)y0;
            int   y1 = min(y0 + 1, HH - 1);
            float sx = (p + 0.5f) * ((float)WW / 16.0f) - 0.5f;
            sx = fmaxf(sx, 0.0f);
            int   x0 = (int)floorf(sx);
            float fx = sx - (float)x0;
            int   x1 = min(x0 + 1, WW - 1);

            float v00 = m[(size_t)y0 * WW + x0];
            float v01 = m[(size_t)y0 * WW + x1];
            float v10 = m[(size_t)y1 * WW + x0];
            float v11 = m[(size_t)y1 * WW + x1];
            float v = (1.0f - fy) * ((1.0f - fx) * v00 + fx * v01)
                    +          fy * ((1.0f - fx) * v10 + fx * v11);

            g_mr[(size_t)bn * SS + tid] = v;
            lsum = v;
        }
        __threadfence();                   // publish g_mr before the flag
        #pragma unroll
        for (int off = 16; off > 0; off >>= 1)
            lsum += __shfl_xor_sync(0xFFFFFFFFu, lsum, off);
        if ((tid & 31) == 0) red[tid >> 5] = lsum;
        __syncthreads();
        if (tid == 0) {
            float s = 0.f;
            #pragma unroll
            for (int i = 0; i < 16; i++) s += red[i];
            g_minv[bn] = 1.0f / (s + 1e-8f);
            __threadfence();
            atomicAdd(&g_ctr, 1);
        }
        return;
    }

    // ---------------- GEMM path (4-way in-block split-K) ----------------
    const int et    = blk >> 6;           // 0..1  (E tile of 64)
    const int stile = blk & 63;           // 0..63
    const int b     = stile >> 2;
    const int s0    = (stile & 3) * 64;
    const int eBase = et * 64;

    const int wg = tid >> 7;              // warpgroup: K-quarter 0..3
    const int lt = tid & 127;
    const int kb = wg << 7;               // K base: 0,128,256,384

    const int te = lt >> 4;               // 0..7  -> e micro-row = te*8
    const int ts = lt & 15;               // 0..15 -> s micro-col = ts*4

    // W load: coalesced row segments, transposed on smem store
    const int wq  = lt & 3;
    const int wei = lt >> 2;              // 0..31 (rows wei, wei+32)
    const float* wp = conv_w + (size_t)(eBase + wei) * CC + kb + (wq << 2);

    // F load: [k][s] coalesced
    const int fk  = lt >> 4;              // 0..7 -> rows fk, fk+8
    const int fsq = (lt & 15) << 2;
    const float* fp = features + ((size_t)b * CC + kb + fk) * SS + s0 + fsq;

    float acc[8][4];
    #pragma unroll
    for (int i = 0; i < 8; i++)
        #pragma unroll
        for (int j = 0; j < 4; j++) acc[i][j] = 0.0f;

    // prefetch K-tile 0 into registers
    float4 wr0 = *(const float4*)wp;
    float4 wr1 = *(const float4*)(wp + 32 * CC);
    float4 fr0 = *(const float4*)fp;
    float4 fr1 = *(const float4*)(fp + 8 * SS);

    #pragma unroll 1
    for (int t = 0; t < 8; t++) {         // 8 K-tiles of 16 = 128 per wg
        __syncthreads();                  // previous tile's compute done
        {
            const int kk = wq << 2;
            SW1(wg, kk + 0, wei) = wr0.x;  SW1(wg, kk + 0, wei + 32) = wr1.x;
            SW1(wg, kk + 1, wei) = wr0.y;  SW1(wg, kk + 1, wei + 32) = wr1.y;
            SW1(wg, kk + 2, wei) = wr0.z;  SW1(wg, kk + 2, wei + 32) = wr1.z;
            SW1(wg, kk + 3, wei) = wr0.w;  SW1(wg, kk + 3, wei + 32) = wr1.w;
            *(float4*)&SF1(wg, fk, fsq)     = fr0;
            *(float4*)&SF1(wg, fk + 8, fsq) = fr1;
        }
        __syncthreads();

        if (t < 7) {                      // prefetch next tile (hidden by FFMA)
            const int c0 = (t + 1) << 4;
            wr0 = *(const float4*)(wp + c0);
            wr1 = *(const float4*)(wp + 32 * CC + c0);
            fr0 = *(const float4*)(fp + (size_t)c0 * SS);
            fr1 = *(const float4*)(fp + (size_t)(c0 + 8) * SS);
        }
        #pragma unroll
        for (int k = 0; k < 16; k++) {
            float4 a0 = *(const float4*)&SW1(wg, k, te << 3);
            float4 a1 = *(const float4*)&SW1(wg, k, (te << 3) + 4);
            float4 f  = *(const float4*)&SF1(wg, k, ts << 2);
            float av[8] = {a0.x, a0.y, a0.z, a0.w, a1.x, a1.y, a1.z, a1.w};
            float fv[4] = {f.x, f.y, f.z, f.w};
            #pragma unroll
            for (int i = 0; i < 8; i++)
                #pragma unroll
                for (int j = 0; j < 4; j++)
                    acc[i][j] += av[i] * fv[j];
        }
    }
    __syncthreads();

    // Combine K-quarters (2-round tree; stageA/stageB are 128x33 = 4224 each).
    {
        float* stageA = sBuf;             // [0, 4224)
        float* stageB = sBuf + 4352;      // [4352, 8576)
        if (wg == 1 || wg == 3) {
            float* st = (wg == 1) ? stageA : stageB;
            #pragma unroll
            for (int i = 0; i < 8; i++)
                #pragma unroll
                for (int j = 0; j < 4; j++)
                    st[lt * 33 + i * 4 + j] = acc[i][j];
        }
        __syncthreads();
        if (wg == 0 || wg == 2) {
            const float* st = (wg == 0) ? stageA : stageB;
            #pragma unroll
            for (int i = 0; i < 8; i++)
                #pragma unroll
                for (int j = 0; j < 4; j++)
                    acc[i][j] += st[lt * 33 + i * 4 + j];
        }
        __syncthreads();
        if (wg == 2) {
            #pragma unroll
            for (int i = 0; i < 8; i++)
                #pragma unroll
                for (int j = 0; j < 4; j++)
                    stageA[lt * 33 + i * 4 + j] = acc[i][j];
        }
        __syncthreads();
        if (wg == 0) {
            #pragma unroll
            for (int i = 0; i < 8; i++)
                #pragma unroll
                for (int j = 0; j < 4; j++)
                    acc[i][j] += stageA[lt * 33 + i * 4 + j];
        }
    }
    __syncthreads();                      // stage reads done; sBuf reusable

    // BN + ReLU in registers (wg0 only), stage proj tile into sBuf (swizzled).
    if (wg == 0) {
        float scv[8], bv[8];
        #pragma unroll
        for (int i = 0; i < 8; i++) {
            const int e = eBase + (te << 3) + i;
            scv[i] = bn_gamma[e] * rsqrtf(bn_var[e] + 1e-5f);
            bv[i]  = (conv_b[e] - bn_mean[e]) * scv[i] + bn_beta[e];
        }
        #pragma unroll
        for (int j = 0; j < 4; j++) {
            const int ls = (ts << 2) + j;
            float4 o0, o1;
            o0.x = fmaxf(acc[0][j] * scv[0] + bv[0], 0.f);
            o0.y = fmaxf(acc[1][j] * scv[1] + bv[1], 0.f);
            o0.z = fmaxf(acc[2][j] * scv[2] + bv[2], 0.f);
            o0.w = fmaxf(acc[3][j] * scv[3] + bv[3], 0.f);
            o1.x = fmaxf(acc[4][j] * scv[4] + bv[4], 0.f);
            o1.y = fmaxf(acc[5][j] * scv[5] + bv[5], 0.f);
            o1.z = fmaxf(acc[6][j] * scv[6] + bv[6], 0.f);
            o1.w = fmaxf(acc[7][j] * scv[7] + bv[7], 0.f);
            *(float4*)&sBuf[sp_idx(ls, (te << 3))]     = o0;
            *(float4*)&sBuf[sp_idx(ls, (te << 3) + 4)] = o1;
        }
    }

    // Wait for all mask blocks.
    if (tid == 0) {
        while (*(volatile int*)&g_ctr < 512) __nanosleep(100);
    }
    __syncthreads();
    __threadfence();

    // Load this block's mask tile [32 n][64 s]
    for (int i = tid; i < NN * 64; i += 512)
        smr[i >> 6][i & 63] = g_mr[(size_t)(b * NN + (i >> 6)) * SS + s0 + (i & 63)];
    __syncthreads();

    // GEMM2: obj_partial[n][e] = sum_ls smr[n][ls] * proj[ls][e]
    // 512 threads: tn = tid>>4 (one n-row each), tc = tid&15 (4 e each)
    {
        const int tn = tid >> 4;          // 0..31
        const int tc = tid & 15;          // e0 = 4*tc
        float ob[4] = {0.f, 0.f, 0.f, 0.f};

        #pragma unroll 4
        for (int ls = 0; ls < 64; ls++) {
            float4 pv = *(const float4*)&sBuf[sp_idx(ls, tc << 2)];
            const float m = smr[tn][ls];
            ob[0] += m * pv.x;
            ob[1] += m * pv.y;
            ob[2] += m * pv.z;
            ob[3] += m * pv.w;
        }
        float* dst = &g_obj[(size_t)(b * NN + tn) * EE + eBase + (tc << 2)];
        #pragma unroll
        for (int c = 0; c < 4; c++)
            atomicAdd(dst + c, ob[c]);
    }
}

// ---------------------------------------------------------------------------
// Kernel B: obj normalize + 2-layer MLP. Grid 128 = (b, ngroup of 4),
// 512 threads: tid = part*128 + e; part splits the 128-k reduction 4 ways.
// Also restores zeroed scratch state for graph replay.
// ---------------------------------------------------------------------------
__global__ void __launch_bounds__(512) kernelB(
    const float* __restrict__ b1, const float* __restrict__ b2,
    float* __restrict__ out)
{
    const int b  = blockIdx.x >> 3;
    const int ng = blockIdx.x & 7;
    const int n0 = ng * 4;
    const int tid  = threadIdx.x;
    const int e    = tid & 127;
    const int part = tid >> 7;           // 0..3

    __shared__ float px[4][4][EE];       // partials [part][row][e]
    __shared__ float xs[4][EE];
    __shared__ float hs[4][EE];
    __shared__ float inv[4];

    if (tid < 4) inv[tid] = g_minv[b * NN + n0 + tid];
    __syncthreads();
    {
        const size_t idx = (size_t)(b * NN + n0 + part) * EE + e;
        xs[part][e] = g_obj[idx] * inv[part];
        g_obj[idx] = 0.f;                 // restore for next graph replay
    }
    if (blockIdx.x == 0 && tid == 0) g_ctr = 0;
    __syncthreads();

    // layer 1 partials over k-quarter (coalesced w1T reads)
    {
        float h0 = 0.f, h1 = 0.f, h2 = 0.f, h3 = 0.f;
        const float* wt = g_w1T + (size_t)(part * 32) * EE + e;
        #pragma unroll 8
        for (int kk = 0; kk < 32; kk++) {
            const float wv = wt[(size_t)kk * EE];
            const int k = part * 32 + kk;
            h0 += wv * xs[0][k];
            h1 += wv * xs[1][k];
            h2 += wv * xs[2][k];
            h3 += wv * xs[3][k];
        }
        px[part][0][e] = h0;
        px[part][1][e] = h1;
        px[part][2][e] = h2;
        px[part][3][e] = h3;
    }
    __syncthreads();

    hs[part][e] = fmaxf(px[0][part][e] + px[1][part][e] + px[2][part][e]
                        + px[3][part][e] + b1[e], 0.f);
    __syncthreads();

    // layer 2 partials
    {
        float h0 = 0.f, h1 = 0.f, h2 = 0.f, h3 = 0.f;
        const float* wt = g_w2T + (size_t)(part * 32) * EE + e;
        #pragma unroll 8
        for (int kk = 0; kk < 32; kk++) {
            const float wv = wt[(size_t)kk * EE];
            const int k = part * 32 + kk;
            h0 += wv * hs[0][k];
            h1 += wv * hs[1][k];
            h2 += wv * hs[2][k];
            h3 += wv * hs[3][k];
        }
        px[part][0][e] = h0;
        px[part][1][e] = h1;
        px[part][2][e] = h2;
        px[part][3][e] = h3;
    }
    __syncthreads();

    out[((size_t)(b * NN + n0 + part)) * EE + e] =
        px[0][part][e] + px[1][part][e] + px[2][part][e] + px[3][part][e] + b2[e];
}

extern "C" void kernel_launch(void* const* d_in, const int* in_sizes, int n_in,
                              void* d_out, int out_size)
{
    const float* features = (const float*)d_in[0];
    const float* masks    = (const float*)d_in[1];
    const float* conv_w   = (const float*)d_in[2];
    const float* conv_b   = (const float*)d_in[3];
    const float* bn_gamma = (const float*)d_in[4];
    const float* bn_beta  = (const float*)d_in[5];
    const float* bn_mean  = (const float*)d_in[6];
    const float* bn_var   = (const float*)d_in[7];
    const float* w1       = (const float*)d_in[8];
    const float* b1       = (const float*)d_in[9];
    const float* w2       = (const float*)d_in[10];
    const float* b2       = (const float*)d_in[11];
    float* out = (float*)d_out;

    kernelA<<<642, 512>>>(features, masks, conv_w, conv_b,
                          bn_gamma, bn_beta, bn_mean, bn_var, w1, w2);
    kernelB<<<128, 512>>>(b1, b2, out);
}

// round 16
// speedup vs baseline: 1.8213x; 1.8213x over previous
#include <cuda_runtime.h>

// Problem constants (fixed by the dataset)
#define BB   16
#define NN   32
#define HH   512
#define WW   512
#define CC   512
#define SS   256    // 16*16 pooled spatial
#define EE   128

// Scratch (static device globals — zero-initialized at load; kernelB restores
// the zeroed state after each use so graph replays stay deterministic).
__device__ float g_obj[BB * NN * EE];    // 256 KB: pooled numerators (REDG accum)
__device__ float g_msum[BB * NN];        // mask sums (REDG accum)
__device__ float g_w1T[EE * EE];         // w1 transposed [k][e]
__device__ float g_w2T[EE * EE];         // w2 transposed [k][e]

// Swizzled index into the 64x64 proj staging tile (quad rotation).
__device__ __forceinline__ int sp_idx(int ls, int e) {
    return ls * 64 + ((((e >> 2) + (ls >> 2)) & 15) << 2) + (e & 3);
}

// Per-warpgroup single-buffered K-tile storage (four independent quarters).
// Each quarter: W tile 16x68 (1088) + F tile 16x68 (1088) = 2176 floats.
#define SW1(g,k,e) sBuf[(g)*2176 + (k)*68 + (e)]
#define SF1(g,k,s) sBuf[(g)*2176 + 1088 + (k)*68 + (s)]

// ---------------------------------------------------------------------------
// Kernel A (512 threads/block, grid 130):
//   blocks [0,128):  self-contained GEMM block: gathers its own 32n x 64s
//                    resized-mask tile (no inter-block sync), runs the
//                    64Ex64S GEMM with 4-way in-block split-K (8Ex4S
//                    microtile, single-buffered 16-k tiles, 4 warps/SMSP),
//                    combines partials, BN/ReLU, pooling GEMM2 -> REDG g_obj.
//                    et=0 blocks also REDG per-n mask sums into g_msum.
//   blocks 128,129:  transpose w1/w2 -> g_w1T/g_w2T.
// ---------------------------------------------------------------------------
__global__ void __launch_bounds__(512) kernelA(
    const float* __restrict__ features,   // [B, C, 16, 16]
    const float* __restrict__ masks,      // [B, N, 512, 512]
    const float* __restrict__ conv_w,     // [E, C]
    const float* __restrict__ conv_b,
    const float* __restrict__ bn_gamma, const float* __restrict__ bn_beta,
    const float* __restrict__ bn_mean,  const float* __restrict__ bn_var,
    const float* __restrict__ w1, const float* __restrict__ w2)
{
    __shared__ float sBuf[8704];          // 4 wg quarters; later stages + sP
    __shared__ float smr[NN][64];         // this block's mask tile [n][local s]

    const int blk = blockIdx.x;
    const int tid = threadIdx.x;

    if (blk >= 128) {
        // ---------------- weight transpose path (aliases sBuf) -------------
        float (*ttile)[33] = (float (*)[33])sBuf;
        const float* src = (blk == 128) ? w1 : w2;
        float* dstT      = (blk == 128) ? g_w1T : g_w2T;
        const int rr = tid >> 5;            // 0..15
        const int cc = tid & 31;
        for (int t = 0; t < 16; t++) {
            const int ti = t >> 2, tj = t & 3;
            #pragma unroll
            for (int q = 0; q < 2; q++) {
                const int row = q * 16 + rr;
                ttile[row][cc] = src[(size_t)(ti * 32 + row) * EE + tj * 32 + cc];
            }
            __syncthreads();
            #pragma unroll
            for (int q = 0; q < 2; q++) {
                const int row = q * 16 + rr;
                dstT[(size_t)(tj * 32 + row) * EE + ti * 32 + cc] = ttile[cc][row];
            }
            __syncthreads();
        }
        return;
    }

    // ---------------- GEMM path (self-contained) ----------------
    const int et    = blk >> 6;           // 0..1  (E tile of 64)
    const int stile = blk & 63;           // 0..63
    const int b     = stile >> 2;
    const int s0    = (stile & 3) * 64;
    const int eBase = et * 64;

    // ---- Mask tile gather: 2048 pixels, 4 per thread. No inter-block sync.
    // Thread (tid, r): idx = tid + 512r -> n = idx>>6, ls = idx&63.
    // All 32 lanes of a warp share n, so a warp-reduce gives the partial sum.
    {
        const int o0 = (stile & 3) * 4;   // pooled-row base for this s-range
        #pragma unroll
        for (int r = 0; r < 4; r++) {
            const int idx = tid + (r << 9);
            const int n = idx >> 6;
            const int ls = idx & 63;
            const int o = o0 + (ls >> 4);
            const int p = ls & 15;
            const float* m = masks + ((size_t)(b * NN + n)) * (HH * WW);

            float sy = (o + 0.5f) * ((float)HH / 16.0f) - 0.5f;
            sy = fmaxf(sy, 0.0f);
            int   y0 = (int)floorf(sy);
            float fy = sy - (float)y0;
            int   y1 = min(y0 + 1, HH - 1);
            float sx = (p + 0.5f) * ((float)WW / 16.0f) - 0.5f;
            sx = fmaxf(sx, 0.0f);
            int   x0 = (int)floorf(sx);
            float fx = sx - (float)x0;
            int   x1 = min(x0 + 1, WW - 1);

            float v00 = m[(size_t)y0 * WW + x0];
            float v01 = m[(size_t)y0 * WW + x1];
            float v10 = m[(size_t)y1 * WW + x0];
            float v11 = m[(size_t)y1 * WW + x1];
            float v = (1.0f - fy) * ((1.0f - fx) * v00 + fx * v01)
                    +          fy * ((1.0f - fx) * v10 + fx * v11);

            smr[n][ls] = v;

            if (et == 0) {                // one E-half contributes the sums
                float wsum = v;
                #pragma unroll
                for (int off = 16; off > 0; off >>= 1)
                    wsum += __shfl_xor_sync(0xFFFFFFFFu, wsum, off);
                if ((tid & 31) == 0)
                    atomicAdd(&g_msum[b * NN + n], wsum);
            }
        }
    }

    // ---- GEMM: 4-way in-block split-K ----
    const int wg = tid >> 7;              // warpgroup: K-quarter 0..3
    const int lt = tid & 127;
    const int kb = wg << 7;               // K base: 0,128,256,384

    const int te = lt >> 4;               // 0..7  -> e micro-row = te*8
    const int ts = lt & 15;               // 0..15 -> s micro-col = ts*4

    // W load: coalesced row segments, transposed on smem store
    const int wq  = lt & 3;
    const int wei = lt >> 2;              // 0..31 (rows wei, wei+32)
    const float* wp = conv_w + (size_t)(eBase + wei) * CC + kb + (wq << 2);

    // F load: [k][s] coalesced
    const int fk  = lt >> 4;              // 0..7 -> rows fk, fk+8
    const int fsq = (lt & 15) << 2;
    const float* fp = features + ((size_t)b * CC + kb + fk) * SS + s0 + fsq;

    float acc[8][4];
    #pragma unroll
    for (int i = 0; i < 8; i++)
        #pragma unroll
        for (int j = 0; j < 4; j++) acc[i][j] = 0.0f;

    // prefetch K-tile 0 into registers
    float4 wr0 = *(const float4*)wp;
    float4 wr1 = *(const float4*)(wp + 32 * CC);
    float4 fr0 = *(const float4*)fp;
    float4 fr1 = *(const float4*)(fp + 8 * SS);

    #pragma unroll 1
    for (int t = 0; t < 8; t++) {         // 8 K-tiles of 16 = 128 per wg
        __syncthreads();                  // previous tile's compute done
        {
            const int kk = wq << 2;
            SW1(wg, kk + 0, wei) = wr0.x;  SW1(wg, kk + 0, wei + 32) = wr1.x;
            SW1(wg, kk + 1, wei) = wr0.y;  SW1(wg, kk + 1, wei + 32) = wr1.y;
            SW1(wg, kk + 2, wei) = wr0.z;  SW1(wg, kk + 2, wei + 32) = wr1.z;
            SW1(wg, kk + 3, wei) = wr0.w;  SW1(wg, kk + 3, wei + 32) = wr1.w;
            *(float4*)&SF1(wg, fk, fsq)     = fr0;
            *(float4*)&SF1(wg, fk + 8, fsq) = fr1;
        }
        __syncthreads();

        if (t < 7) {                      // prefetch next tile (hidden by FFMA)
            const int c0 = (t + 1) << 4;
            wr0 = *(const float4*)(wp + c0);
            wr1 = *(const float4*)(wp + 32 * CC + c0);
            fr0 = *(const float4*)(fp + (size_t)c0 * SS);
            fr1 = *(const float4*)(fp + (size_t)(c0 + 8) * SS);
        }
        #pragma unroll
        for (int k = 0; k < 16; k++) {
            float4 a0 = *(const float4*)&SW1(wg, k, te << 3);
            float4 a1 = *(const float4*)&SW1(wg, k, (te << 3) + 4);
            float4 f  = *(const float4*)&SF1(wg, k, ts << 2);
            float av[8] = {a0.x, a0.y, a0.z, a0.w, a1.x, a1.y, a1.z, a1.w};
            float fv[4] = {f.x, f.y, f.z, f.w};
            #pragma unroll
            for (int i = 0; i < 8; i++)
                #pragma unroll
                for (int j = 0; j < 4; j++)
                    acc[i][j] += av[i] * fv[j];
        }
    }
    __syncthreads();

    // Combine K-quarters (2-round tree; stageA/stageB are 128x33 = 4224 each).
    {
        float* stageA = sBuf;             // [0, 4224)
        float* stageB = sBuf + 4352;      // [4352, 8576)
        if (wg == 1 || wg == 3) {
            float* st = (wg == 1) ? stageA : stageB;
            #pragma unroll
            for (int i = 0; i < 8; i++)
                #pragma unroll
                for (int j = 0; j < 4; j++)
                    st[lt * 33 + i * 4 + j] = acc[i][j];
        }
        __syncthreads();
        if (wg == 0 || wg == 2) {
            const float* st = (wg == 0) ? stageA : stageB;
            #pragma unroll
            for (int i = 0; i < 8; i++)
                #pragma unroll
                for (int j = 0; j < 4; j++)
                    acc[i][j] += st[lt * 33 + i * 4 + j];
        }
        __syncthreads();
        if (wg == 2) {
            #pragma unroll
            for (int i = 0; i < 8; i++)
                #pragma unroll
                for (int j = 0; j < 4; j++)
                    stageA[lt * 33 + i * 4 + j] = acc[i][j];
        }
        __syncthreads();
        if (wg == 0) {
            #pragma unroll
            for (int i = 0; i < 8; i++)
                #pragma unroll
                for (int j = 0; j < 4; j++)
                    acc[i][j] += stageA[lt * 33 + i * 4 + j];
        }
    }
    __syncthreads();                      // stage reads done; sBuf reusable

    // BN + ReLU in registers (wg0 only), stage proj tile into sBuf (swizzled).
    if (wg == 0) {
        float scv[8], bv[8];
        #pragma unroll
        for (int i = 0; i < 8; i++) {
            const int e = eBase + (te << 3) + i;
            scv[i] = bn_gamma[e] * rsqrtf(bn_var[e] + 1e-5f);
            bv[i]  = (conv_b[e] - bn_mean[e]) * scv[i] + bn_beta[e];
        }
        #pragma unroll
        for (int j = 0; j < 4; j++) {
            const int ls = (ts << 2) + j;
            float4 o0, o1;
            o0.x = fmaxf(acc[0][j] * scv[0] + bv[0], 0.f);
            o0.y = fmaxf(acc[1][j] * scv[1] + bv[1], 0.f);
            o0.z = fmaxf(acc[2][j] * scv[2] + bv[2], 0.f);
            o0.w = fmaxf(acc[3][j] * scv[3] + bv[3], 0.f);
            o1.x = fmaxf(acc[4][j] * scv[4] + bv[4], 0.f);
            o1.y = fmaxf(acc[5][j] * scv[5] + bv[5], 0.f);
            o1.z = fmaxf(acc[6][j] * scv[6] + bv[6], 0.f);
            o1.w = fmaxf(acc[7][j] * scv[7] + bv[7], 0.f);
            *(float4*)&sBuf[sp_idx(ls, (te << 3))]     = o0;
            *(float4*)&sBuf[sp_idx(ls, (te << 3) + 4)] = o1;
        }
    }
    __syncthreads();

    // GEMM2: obj_partial[n][e] = sum_ls smr[n][ls] * proj[ls][e]
    // 512 threads: tn = tid>>4 (one n-row each), tc = tid&15 (4 e each)
    {
        const int tn = tid >> 4;          // 0..31
        const int tc = tid & 15;          // e0 = 4*tc
        float ob[4] = {0.f, 0.f, 0.f, 0.f};

        #pragma unroll 4
        for (int ls = 0; ls < 64; ls++) {
            float4 pv = *(const float4*)&sBuf[sp_idx(ls, tc << 2)];
            const float m = smr[tn][ls];
            ob[0] += m * pv.x;
            ob[1] += m * pv.y;
            ob[2] += m * pv.z;
            ob[3] += m * pv.w;
        }
        float* dst = &g_obj[(size_t)(b * NN + tn) * EE + eBase + (tc << 2)];
        #pragma unroll
        for (int c = 0; c < 4; c++)
            atomicAdd(dst + c, ob[c]);
    }
}

// ---------------------------------------------------------------------------
// Kernel B: obj normalize (1/(msum+eps) computed here) + 2-layer MLP.
// Grid 128 = (b, ngroup of 4), 512 threads: tid = part*128 + e.
// Also restores zeroed scratch state (g_obj, g_msum) for graph replay.
// ---------------------------------------------------------------------------
__global__ void __launch_bounds__(512) kernelB(
    const float* __restrict__ b1, const float* __restrict__ b2,
    float* __restrict__ out)
{
    const int b  = blockIdx.x >> 3;
    const int ng = blockIdx.x & 7;
    const int n0 = ng * 4;
    const int tid  = threadIdx.x;
    const int e    = tid & 127;
    const int part = tid >> 7;           // 0..3

    __shared__ float px[4][4][EE];       // partials [part][row][e]
    __shared__ float xs[4][EE];
    __shared__ float hs[4][EE];
    __shared__ float inv[4];

    if (tid < 4) {
        const int bn = b * NN + n0 + tid;
        inv[tid] = 1.0f / (g_msum[bn] + 1e-8f);
        g_msum[bn] = 0.f;                 // restore for next graph replay
    }
    __syncthreads();
    {
        const size_t idx = (size_t)(b * NN + n0 + part) * EE + e;
        xs[part][e] = g_obj[idx] * inv[part];
        g_obj[idx] = 0.f;                 // restore for next graph replay
    }
    __syncthreads();

    // layer 1 partials over k-quarter (coalesced w1T reads)
    {
        float h0 = 0.f, h1 = 0.f, h2 = 0.f, h3 = 0.f;
        const float* wt = g_w1T + (size_t)(part * 32) * EE + e;
        #pragma unroll 8
        for (int kk = 0; kk < 32; kk++) {
            const float wv = wt[(size_t)kk * EE];
            const int k = part * 32 + kk;
            h0 += wv * xs[0][k];
            h1 += wv * xs[1][k];
            h2 += wv * xs[2][k];
            h3 += wv * xs[3][k];
        }
        px[part][0][e] = h0;
        px[part][1][e] = h1;
        px[part][2][e] = h2;
        px[part][3][e] = h3;
    }
    __syncthreads();

    hs[part][e] = fmaxf(px[0][part][e] + px[1][part][e] + px[2][part][e]
                        + px[3][part][e] + b1[e], 0.f);
    __syncthreads();

    // layer 2 partials
    {
        float h0 = 0.f, h1 = 0.f, h2 = 0.f, h3 = 0.f;
        const float* wt = g_w2T + (size_t)(part * 32) * EE + e;
        #pragma unroll 8
        for (int kk = 0; kk < 32; kk++) {
            const float wv = wt[(size_t)kk * EE];
            const int k = part * 32 + kk;
            h0 += wv * hs[0][k];
            h1 += wv * hs[1][k];
            h2 += wv * hs[2][k];
            h3 += wv * hs[3][k];
        }
        px[part][0][e] = h0;
        px[part][1][e] = h1;
        px[part][2][e] = h2;
        px[part][3][e] = h3;
    }
    __syncthreads();

    out[((size_t)(b * NN + n0 + part)) * EE + e] =
        px[0][part][e] + px[1][part][e] + px[2][part][e] + px[3][part][e] + b2[e];
}

extern "C" void kernel_launch(void* const* d_in, const int* in_sizes, int n_in,
                              void* d_out, int out_size)
{
    const float* features = (const float*)d_in[0];
    const float* masks    = (const float*)d_in[1];
    const float* conv_w   = (const float*)d_in[2];
    const float* conv_b   = (const float*)d_in[3];
    const float* bn_gamma = (const float*)d_in[4];
    const float* bn_beta  = (const float*)d_in[5];
    const float* bn_mean  = (const float*)d_in[6];
    const float* bn_var   = (const float*)d_in[7];
    const float* w1       = (const float*)d_in[8];
    const float* b1       = (const float*)d_in[9];
    const float* w2       = (const float*)d_in[10];
    const float* b2       = (const float*)d_in[11];
    float* out = (float*)d_out;

    kernelA<<<130, 512>>>(features, masks, conv_w, conv_b,
                          bn_gamma, bn_beta, bn_mean, bn_var, w1, w2);
    kernelB<<<128, 512>>>(b1, b2, out);
}